// round 16
// baseline (speedup 1.0000x reference)
#include <cuda_runtime.h>
#include <cuda_bf16.h>
#include <math.h>
#include <stdint.h>

// x: (16, 256, 64, 64, 4) f32. Per (b,c) slab = 4096 float4 = 64 KB.
// R15 structure (PDL serial chain, role-separated blocks) with chunk = 1
// batch = 16 MB:
//   L0: pool(b0); Lk: combined scale(b_{k-1})+pool(b_k) k=1..15; L16: scale(b15)
// Every launch uses programmatic stream serialization; all blocks trigger
// launch completion at entry; only SCALE blocks grid-dependency-sync.
// Pool unit = full slab (64 KB DRAM read). Scale unit = half slab
// (32 KB __ldcs L2 read + 32 KB __stcs streamed write).
// Steady-state L2 footprint = 2 batches + writes ~ 48 MB << 126 MB.

#define NB 16
#define NC 256
#define SP 4096                      // float4 per (b,c)
#define HSP (SP / 2)
#define TPB 256
#define GRP 8

__device__ float4 g_pooled[NB * NC];

// ---------------------------------------------------------------------------
__device__ __forceinline__ void do_pool(const float* __restrict__ x, int bc) {
    const float4* xp = reinterpret_cast<const float4*>(x) + (size_t)bc * SP;
    const int t = threadIdx.x;

    float4 m = make_float4(-INFINITY, -INFINITY, -INFINITY, -INFINITY);
    #pragma unroll
    for (int j0 = 0; j0 < SP / TPB; j0 += GRP) {
        float4 v[GRP];
        #pragma unroll
        for (int j = 0; j < GRP; j++) v[j] = xp[t + (j0 + j) * TPB];
        #pragma unroll
        for (int j = 0; j < GRP; j++) {
            m.x = fmaxf(m.x, v[j].x);
            m.y = fmaxf(m.y, v[j].y);
            m.z = fmaxf(m.z, v[j].z);
            m.w = fmaxf(m.w, v[j].w);
        }
    }
    #pragma unroll
    for (int o = 16; o > 0; o >>= 1) {
        m.x = fmaxf(m.x, __shfl_xor_sync(0xffffffffu, m.x, o));
        m.y = fmaxf(m.y, __shfl_xor_sync(0xffffffffu, m.y, o));
        m.z = fmaxf(m.z, __shfl_xor_sync(0xffffffffu, m.z, o));
        m.w = fmaxf(m.w, __shfl_xor_sync(0xffffffffu, m.w, o));
    }
    __shared__ float4 red[TPB / 32];
    if ((t & 31) == 0) red[t >> 5] = m;
    __syncthreads();
    if (t == 0) {
        float4 r = red[0];
        #pragma unroll
        for (int w = 1; w < TPB / 32; w++) {
            r.x = fmaxf(r.x, red[w].x);
            r.y = fmaxf(r.y, red[w].y);
            r.z = fmaxf(r.z, red[w].z);
            r.w = fmaxf(r.w, red[w].w);
        }
        g_pooled[bc] = r;
    }
}

// ---------------------------------------------------------------------------
__device__ __forceinline__ void do_scale_half(const float* __restrict__ x,
                                              const float* __restrict__ comp_w,
                                              const float* __restrict__ comp_b,
                                              const float* __restrict__ exc_w,
                                              const float* __restrict__ exc_b,
                                              float* __restrict__ out,
                                              int bc, int half) {
    const int b = bc >> 8;
    const int c = bc & 255;
    const int t = threadIdx.x;
    const int lane = t & 31;
    const int warp = t >> 5;

    __shared__ float4 red[TPB / 32];
    __shared__ float4 u_sh;

    float4 p = g_pooled[b * NC + t];
    float s0 = p.x * comp_w[0 * NC + t];
    float s1 = p.y * comp_w[1 * NC + t];
    float s2 = p.z * comp_w[2 * NC + t];
    float s3 = p.w * comp_w[3 * NC + t];
    #pragma unroll
    for (int o = 16; o > 0; o >>= 1) {
        s0 += __shfl_xor_sync(0xffffffffu, s0, o);
        s1 += __shfl_xor_sync(0xffffffffu, s1, o);
        s2 += __shfl_xor_sync(0xffffffffu, s2, o);
        s3 += __shfl_xor_sync(0xffffffffu, s3, o);
    }
    if (lane == 0) red[warp] = make_float4(s0, s1, s2, s3);
    __syncthreads();
    if (t == 0) {
        float r  = comp_b[0];
        float xc = comp_b[1];
        float yc = comp_b[2];
        float zc = comp_b[3];
        #pragma unroll
        for (int w = 0; w < TPB / 32; w++) {
            r  += red[w].x;
            xc += red[w].y;
            yc += red[w].z;
            zc += red[w].w;
        }
        float u1r = r + xc + yc + zc;
        float u1x = xc - r - zc + yc;
        float u1y = yc + zc - r - xc;
        float u1z = zc - yc + xc - r;
        float r2 = u1r * exc_w[0 * NC + c] + exc_b[0 * NC + c];
        float x2 = u1x * exc_w[1 * NC + c] + exc_b[1 * NC + c];
        float y2 = u1y * exc_w[2 * NC + c] + exc_b[2 * NC + c];
        float z2 = u1z * exc_w[3 * NC + c] + exc_b[3 * NC + c];
        u_sh = make_float4(r2 + x2 + y2 + z2,
                           x2 - r2 - z2 + y2,
                           y2 + z2 - r2 - x2,
                           z2 - y2 + x2 - r2);
    }
    __syncthreads();
    const float4 u = u_sh;

    const size_t base = (size_t)bc * SP + (size_t)half * HSP;
    const float4* xp = reinterpret_cast<const float4*>(x) + base;
    float4* op = reinterpret_cast<float4*>(out) + base;
    float4 v[GRP];
    #pragma unroll
    for (int j = 0; j < GRP; j++) v[j] = __ldcs(&xp[t + j * TPB]);
    #pragma unroll
    for (int j = 0; j < GRP; j++) {
        __stcs(&op[t + j * TPB],
               make_float4(v[j].x * u.x, v[j].y * u.y,
                           v[j].z * u.z, v[j].w * u.w));
    }
}

// ---------------------------------------------------------------------------
__global__ void __launch_bounds__(TPB) pool_only_kernel(const float* __restrict__ x,
                                                        int b0) {
    cudaTriggerProgrammaticLaunchCompletion();
    do_pool(x, b0 * NC + blockIdx.x);
}

__global__ void __launch_bounds__(TPB) scale_only_kernel(const float* __restrict__ x,
                                                         const float* __restrict__ comp_w,
                                                         const float* __restrict__ comp_b,
                                                         const float* __restrict__ exc_w,
                                                         const float* __restrict__ exc_b,
                                                         float* __restrict__ out,
                                                         int b0) {
    cudaTriggerProgrammaticLaunchCompletion();
    cudaGridDependencySynchronize();
    do_scale_half(x, comp_w, comp_b, exc_w, exc_b, out,
                  b0 * NC + (int)(blockIdx.x >> 1), blockIdx.x & 1);
}

__global__ void __launch_bounds__(TPB) combined_kernel(const float* __restrict__ x,
                                                       const float* __restrict__ comp_w,
                                                       const float* __restrict__ comp_b,
                                                       const float* __restrict__ exc_w,
                                                       const float* __restrict__ exc_b,
                                                       float* __restrict__ out,
                                                       int scale_b0, int pool_b0) {
    cudaTriggerProgrammaticLaunchCompletion();
    const int sid  = blockIdx.x / 3;
    const int role = blockIdx.x % 3;
    if (role == 0) {
        do_pool(x, pool_b0 * NC + sid);
    } else {
        cudaGridDependencySynchronize();
        do_scale_half(x, comp_w, comp_b, exc_w, exc_b, out,
                      scale_b0 * NC + sid, role - 1);
    }
}

// ---------------------------------------------------------------------------
template <typename... Args>
static inline void launch_pdl(void (*kern)(Args...), int grid, Args... args) {
    cudaLaunchConfig_t cfg = {};
    cfg.gridDim = dim3(grid);
    cfg.blockDim = dim3(TPB);
    cfg.dynamicSmemBytes = 0;
    cfg.stream = 0;
    cudaLaunchAttribute attr[1];
    attr[0].id = cudaLaunchAttributeProgrammaticStreamSerialization;
    attr[0].val.programmaticStreamSerializationAllowed = 1;
    cfg.attrs = attr;
    cfg.numAttrs = 1;
    cudaLaunchKernelEx(&cfg, kern, args...);
}

extern "C" void kernel_launch(void* const* d_in, const int* in_sizes, int n_in,
                              void* d_out, int out_size) {
    const float* x      = (const float*)d_in[0];
    const float* comp_w = (const float*)d_in[1];
    const float* comp_b = (const float*)d_in[2];
    const float* exc_w  = (const float*)d_in[3];
    const float* exc_b  = (const float*)d_in[4];
    float* out = (float*)d_out;

    // Chunk = 1 batch. L0: pool(b0); L1..15: scale(b-1)+pool(b); L16: scale(b15)
    launch_pdl(pool_only_kernel, NC, x, 0);
    for (int b = 1; b < NB; b++) {
        launch_pdl(combined_kernel, 3 * NC,
                   x, comp_w, comp_b, exc_w, exc_b, out, b - 1, b);
    }
    launch_pdl(scale_only_kernel, 2 * NC,
               x, comp_w, comp_b, exc_w, exc_b, out, NB - 1);
}

// round 17
// speedup vs baseline: 1.0840x; 1.0840x over previous
#include <cuda_runtime.h>
#include <cuda_bf16.h>
#include <math.h>
#include <stdint.h>

// x: (16, 256, 64, 64, 4) f32. Per (b,c) slab = 4096 float4 = 64 KB.
// R15 (PDL serial chain, role-separated blocks, chunk=2 batches) with the
// FINAL chunk split in two: chunks [2,2,2,2,2,2,2,1,1].
//   L0: pool(c0)
//   Lk: combined scale(c_{k-1}) + pool(c_k), k=1..8   (Bresenham interleave)
//   L9: scale(c8)  -- only 16 MB of write-only tail instead of 32 MB
// Pool unit = full slab (64 KB DRAM read). Scale unit = half slab
// (32 KB __ldcs L2 read + 32 KB __stcs streamed write).
// PDL: all launches programmatic-serialization; all blocks trigger launch
// completion at entry; only scale blocks grid-dependency-sync.

#define NB 16
#define NC 256
#define SP 4096                      // float4 per (b,c)
#define HSP (SP / 2)
#define TPB 256
#define GRP 8

__device__ float4 g_pooled[NB * NC];

// ---------------------------------------------------------------------------
__device__ __forceinline__ void do_pool(const float* __restrict__ x, int bc) {
    const float4* xp = reinterpret_cast<const float4*>(x) + (size_t)bc * SP;
    const int t = threadIdx.x;

    float4 m = make_float4(-INFINITY, -INFINITY, -INFINITY, -INFINITY);
    #pragma unroll
    for (int j0 = 0; j0 < SP / TPB; j0 += GRP) {
        float4 v[GRP];
        #pragma unroll
        for (int j = 0; j < GRP; j++) v[j] = xp[t + (j0 + j) * TPB];
        #pragma unroll
        for (int j = 0; j < GRP; j++) {
            m.x = fmaxf(m.x, v[j].x);
            m.y = fmaxf(m.y, v[j].y);
            m.z = fmaxf(m.z, v[j].z);
            m.w = fmaxf(m.w, v[j].w);
        }
    }
    #pragma unroll
    for (int o = 16; o > 0; o >>= 1) {
        m.x = fmaxf(m.x, __shfl_xor_sync(0xffffffffu, m.x, o));
        m.y = fmaxf(m.y, __shfl_xor_sync(0xffffffffu, m.y, o));
        m.z = fmaxf(m.z, __shfl_xor_sync(0xffffffffu, m.z, o));
        m.w = fmaxf(m.w, __shfl_xor_sync(0xffffffffu, m.w, o));
    }
    __shared__ float4 red[TPB / 32];
    if ((t & 31) == 0) red[t >> 5] = m;
    __syncthreads();
    if (t == 0) {
        float4 r = red[0];
        #pragma unroll
        for (int w = 1; w < TPB / 32; w++) {
            r.x = fmaxf(r.x, red[w].x);
            r.y = fmaxf(r.y, red[w].y);
            r.z = fmaxf(r.z, red[w].z);
            r.w = fmaxf(r.w, red[w].w);
        }
        g_pooled[bc] = r;
    }
}

// ---------------------------------------------------------------------------
__device__ __forceinline__ void do_scale_half(const float* __restrict__ x,
                                              const float* __restrict__ comp_w,
                                              const float* __restrict__ comp_b,
                                              const float* __restrict__ exc_w,
                                              const float* __restrict__ exc_b,
                                              float* __restrict__ out,
                                              int bc, int half) {
    const int b = bc >> 8;
    const int c = bc & 255;
    const int t = threadIdx.x;
    const int lane = t & 31;
    const int warp = t >> 5;

    __shared__ float4 red[TPB / 32];
    __shared__ float4 u_sh;

    float4 p = g_pooled[b * NC + t];
    float s0 = p.x * comp_w[0 * NC + t];
    float s1 = p.y * comp_w[1 * NC + t];
    float s2 = p.z * comp_w[2 * NC + t];
    float s3 = p.w * comp_w[3 * NC + t];
    #pragma unroll
    for (int o = 16; o > 0; o >>= 1) {
        s0 += __shfl_xor_sync(0xffffffffu, s0, o);
        s1 += __shfl_xor_sync(0xffffffffu, s1, o);
        s2 += __shfl_xor_sync(0xffffffffu, s2, o);
        s3 += __shfl_xor_sync(0xffffffffu, s3, o);
    }
    if (lane == 0) red[warp] = make_float4(s0, s1, s2, s3);
    __syncthreads();
    if (t == 0) {
        float r  = comp_b[0];
        float xc = comp_b[1];
        float yc = comp_b[2];
        float zc = comp_b[3];
        #pragma unroll
        for (int w = 0; w < TPB / 32; w++) {
            r  += red[w].x;
            xc += red[w].y;
            yc += red[w].z;
            zc += red[w].w;
        }
        float u1r = r + xc + yc + zc;
        float u1x = xc - r - zc + yc;
        float u1y = yc + zc - r - xc;
        float u1z = zc - yc + xc - r;
        float r2 = u1r * exc_w[0 * NC + c] + exc_b[0 * NC + c];
        float x2 = u1x * exc_w[1 * NC + c] + exc_b[1 * NC + c];
        float y2 = u1y * exc_w[2 * NC + c] + exc_b[2 * NC + c];
        float z2 = u1z * exc_w[3 * NC + c] + exc_b[3 * NC + c];
        u_sh = make_float4(r2 + x2 + y2 + z2,
                           x2 - r2 - z2 + y2,
                           y2 + z2 - r2 - x2,
                           z2 - y2 + x2 - r2);
    }
    __syncthreads();
    const float4 u = u_sh;

    const size_t base = (size_t)bc * SP + (size_t)half * HSP;
    const float4* xp = reinterpret_cast<const float4*>(x) + base;
    float4* op = reinterpret_cast<float4*>(out) + base;
    float4 v[GRP];
    #pragma unroll
    for (int j = 0; j < GRP; j++) v[j] = __ldcs(&xp[t + j * TPB]);
    #pragma unroll
    for (int j = 0; j < GRP; j++) {
        __stcs(&op[t + j * TPB],
               make_float4(v[j].x * u.x, v[j].y * u.y,
                           v[j].z * u.z, v[j].w * u.w));
    }
}

// ---------------------------------------------------------------------------
// Generic PDL step: np pool units (full slabs from pool_b0) and ns scale
// units (half slabs from scale_b0), Bresenham-interleaved over np+ns blocks.
// ---------------------------------------------------------------------------
__global__ void __launch_bounds__(TPB) step_kernel(const float* __restrict__ x,
                                                   const float* __restrict__ comp_w,
                                                   const float* __restrict__ comp_b,
                                                   const float* __restrict__ exc_w,
                                                   const float* __restrict__ exc_b,
                                                   float* __restrict__ out,
                                                   int scale_b0, int ns,
                                                   int pool_b0, int np) {
    cudaTriggerProgrammaticLaunchCompletion();
    const long r = blockIdx.x;
    const long tot = np + ns;
    const int p_lo = (int)((r * np) / tot);
    const int p_hi = (int)(((r + 1) * np) / tot);
    if (p_hi > p_lo) {
        // Pool: no dependency on the previous launch -> start immediately.
        do_pool(x, pool_b0 * NC + p_lo);
    } else {
        // Scale: needs g_pooled from the previous launch.
        cudaGridDependencySynchronize();
        const int sidx = (int)r - p_hi;
        do_scale_half(x, comp_w, comp_b, exc_w, exc_b, out,
                      scale_b0 * NC + (sidx >> 1), sidx & 1);
    }
}

// ---------------------------------------------------------------------------
static inline void launch_step(const float* x, const float* comp_w,
                               const float* comp_b, const float* exc_w,
                               const float* exc_b, float* out,
                               int scale_b0, int ns, int pool_b0, int np) {
    cudaLaunchConfig_t cfg = {};
    cfg.gridDim = dim3(np + ns);
    cfg.blockDim = dim3(TPB);
    cfg.dynamicSmemBytes = 0;
    cfg.stream = 0;
    cudaLaunchAttribute attr[1];
    attr[0].id = cudaLaunchAttributeProgrammaticStreamSerialization;
    attr[0].val.programmaticStreamSerializationAllowed = 1;
    cfg.attrs = attr;
    cfg.numAttrs = 1;
    cudaLaunchKernelEx(&cfg, step_kernel, x, comp_w, comp_b, exc_w, exc_b,
                       out, scale_b0, ns, pool_b0, np);
}

extern "C" void kernel_launch(void* const* d_in, const int* in_sizes, int n_in,
                              void* d_out, int out_size) {
    const float* x      = (const float*)d_in[0];
    const float* comp_w = (const float*)d_in[1];
    const float* comp_b = (const float*)d_in[2];
    const float* exc_w  = (const float*)d_in[3];
    const float* exc_b  = (const float*)d_in[4];
    float* out = (float*)d_out;

    // Chunk table: sizes 2,2,2,2,2,2,2,1,1 (batch start / count).
    const int cb[9] = {0, 2, 4, 6, 8, 10, 12, 14, 15};
    const int cn[9] = {2, 2, 2, 2, 2, 2, 2, 1, 1};

    // L0: pool chunk 0
    launch_step(x, comp_w, comp_b, exc_w, exc_b, out,
                0, 0, cb[0], cn[0] * NC);
    // L1..L8: combined scale(c_{k-1}) + pool(c_k)
    for (int k = 1; k <= 8; k++) {
        launch_step(x, comp_w, comp_b, exc_w, exc_b, out,
                    cb[k - 1], cn[k - 1] * NC * 2,
                    cb[k], cn[k] * NC);
    }
    // L9: scale chunk 8 (16 MB write-only tail)
    launch_step(x, comp_w, comp_b, exc_w, exc_b, out,
                cb[8], cn[8] * NC * 2, 0, 0);
}